// round 5
// baseline (speedup 1.0000x reference)
#include <cuda_runtime.h>
#include <cuda_bf16.h>

// pred (16,54,192,192) f32, target (16,6,192,192) f32, loc unused.
// loss = [ bce_sum(pred[:,0:18:2], target[:,0:1]) +
//          bce_sum(pred[:,1:18:2], target[:,1:2]) ] / 9
// Per pixel & parity pr: sum_{c=0..8} softplus(x_{pr+2c}) - t_pr * sum_c x_{pr+2c}
// (softplus(x) = max(x,0) + log1p(exp(-|x|)))

namespace {
constexpr int B        = 16;
constexpr int H        = 192;
constexpr int W        = 192;
constexpr int HW       = H * W;        // 36864
constexpr int HW4      = HW / 4;       // 9216 float4 per channel slice
constexpr int NPAIR    = 9;            // channels per parity
constexpr int PRED_CH  = 54;
constexpr int TGT_CH   = 6;

constexpr int TPB      = 256;
constexpr int CHUNKS   = HW4 / TPB;          // 36 chunks per (batch, parity)
constexpr int NBLOCKS  = B * 2 * CHUNKS;     // 1152
}

__device__ float        g_partials[NBLOCKS];
__device__ unsigned int g_count = 0;

__device__ __forceinline__ float softplus_t(float x) {
    // max(x,0) + log1p(exp(-|x|))
    float ax = fabsf(x);
    float e  = __expf(-ax);                       // MUFU.EX2
    return fmaxf(x, 0.0f) + __logf(1.0f + e);     // MUFU.LG2
}

__device__ __forceinline__ float block_reduce(float acc) {
    #pragma unroll
    for (int o = 16; o > 0; o >>= 1)
        acc += __shfl_xor_sync(0xffffffffu, acc, o);
    __shared__ float s[TPB / 32];
    if ((threadIdx.x & 31) == 0) s[threadIdx.x >> 5] = acc;
    __syncthreads();
    float v = 0.0f;
    if (threadIdx.x < 32) {
        v = (threadIdx.x < TPB / 32) ? s[threadIdx.x] : 0.0f;
        #pragma unroll
        for (int o = 4; o > 0; o >>= 1)
            v += __shfl_xor_sync(0xffffffffu, v, o);
    }
    return v;  // valid in thread 0
}

__global__ __launch_bounds__(TPB)
void rpn_bce_fused(const float4* __restrict__ pred,
                   const float4* __restrict__ target,
                   float* __restrict__ out) {
    const int bid    = blockIdx.x;               // 0..1151
    const int chunk  = bid % CHUNKS;             // 0..35
    const int bp     = bid / CHUNKS;             // 0..31
    const int parity = bp & 1;
    const int b      = bp >> 1;

    const int pix = chunk * TPB + threadIdx.x;   // float4 pixel index

    const float4* __restrict__ p =
        pred + ((size_t)b * PRED_CH + parity) * HW4 + pix;   // + c*2*HW4
    const float4 t =
        __ldg(target + ((size_t)b * TGT_CH + parity) * HW4 + pix);

    // 9 independent channel loads (stride 2*HW4) -> high per-thread MLP.
    float4 xs[NPAIR];
    #pragma unroll
    for (int c = 0; c < NPAIR; ++c)
        xs[c] = __ldg(p + (size_t)c * (2 * HW4));

    float4 sp = make_float4(0.f, 0.f, 0.f, 0.f);   // sum softplus
    float4 xa = make_float4(0.f, 0.f, 0.f, 0.f);   // sum x
    #pragma unroll
    for (int c = 0; c < NPAIR; ++c) {
        sp.x += softplus_t(xs[c].x);  xa.x += xs[c].x;
        sp.y += softplus_t(xs[c].y);  xa.y += xs[c].y;
        sp.z += softplus_t(xs[c].z);  xa.z += xs[c].z;
        sp.w += softplus_t(xs[c].w);  xa.w += xs[c].w;
    }

    float acc = (sp.x - t.x * xa.x) + (sp.y - t.y * xa.y)
              + (sp.z - t.z * xa.z) + (sp.w - t.w * xa.w);

    const float v = block_reduce(acc);

    // Last-block-done deterministic finalize.
    __shared__ bool s_last;
    if (threadIdx.x == 0) {
        g_partials[bid] = v;
        __threadfence();
        unsigned int n = atomicAdd(&g_count, 1u);
        s_last = (n == (unsigned int)(NBLOCKS - 1));
    }
    __syncthreads();

    if (s_last) {
        __threadfence();
        float a = 0.0f;
        #pragma unroll
        for (int i = threadIdx.x; i < NBLOCKS; i += TPB)
            a += g_partials[i];
        const float total = block_reduce(a);
        if (threadIdx.x == 0) {
            out[0] = total * (1.0f / 9.0f);     // / NUM_OBJ_CLS
            g_count = 0;                        // reset for graph replays
        }
    }
}

extern "C" void kernel_launch(void* const* d_in, const int* in_sizes, int n_in,
                              void* d_out, int out_size) {
    (void)in_sizes; (void)n_in; (void)out_size;
    const float4* pred   = (const float4*)d_in[0];
    const float4* target = (const float4*)d_in[1];
    float* out = (float*)d_out;

    rpn_bce_fused<<<NBLOCKS, TPB>>>(pred, target, out);
}

// round 6
// speedup vs baseline: 1.0251x; 1.0251x over previous
#include <cuda_runtime.h>
#include <cuda_bf16.h>

// pred (16,54,192,192) f32, target (16,6,192,192) f32, loc unused.
// loss = [ bce_sum(pred[:,0:18:2], target[:,0:1]) +
//          bce_sum(pred[:,1:18:2], target[:,1:2]) ] / 9
// Pred channel ch (0..17) pairs with target channel (ch & 1).
// Per element: max(x,0) - x*t + log1p(exp(-|x|)).
// Trick: sum_i log1p(e_i) = ln( prod_i (1+e_i) ), e_i in (0,1] so a
// 4-element product is in (1,16] -> one LG2 per float4 instead of 4.

namespace {
constexpr int B        = 16;
constexpr int HW4      = 192 * 192 / 4;      // 9216 float4 per channel slice
constexpr int NCH      = 18;
constexpr int PRED_CH  = 54;
constexpr int TGT_CH   = 6;

constexpr int TPB      = 256;
constexpr int SPLIT    = 4;                  // hw chunks per slice
constexpr int CHUNK4   = HW4 / SPLIT;        // 2304 float4 per block
constexpr int ITERS    = CHUNK4 / TPB;       // 9 float4 per thread
constexpr int NSLICES  = B * NCH;            // 288
constexpr int NBLOCKS  = NSLICES * SPLIT;    // 1152 (single wave @ 8 blk/SM)
}

__device__ float        g_partials[NBLOCKS];
__device__ unsigned int g_count = 0;

__device__ __forceinline__ float block_reduce(float acc) {
    #pragma unroll
    for (int o = 16; o > 0; o >>= 1)
        acc += __shfl_xor_sync(0xffffffffu, acc, o);
    __shared__ float s[TPB / 32];
    if ((threadIdx.x & 31) == 0) s[threadIdx.x >> 5] = acc;
    __syncthreads();
    float v = 0.0f;
    if (threadIdx.x < 32) {
        v = (threadIdx.x < TPB / 32) ? s[threadIdx.x] : 0.0f;
        #pragma unroll
        for (int o = 4; o > 0; o >>= 1)
            v += __shfl_xor_sync(0xffffffffu, v, o);
    }
    return v;  // valid in thread 0
}

__global__ __launch_bounds__(TPB, 8)   // cap regs at 32 -> 8 blocks/SM, 1 wave
void rpn_bce_fused(const float4* __restrict__ pred,
                   const float4* __restrict__ target,
                   float* __restrict__ out) {
    const int bid   = blockIdx.x;
    const int chunk = bid % SPLIT;
    const int slice = bid / SPLIT;           // 0..287
    const int ch    = slice % NCH;           // pred channel 0..17
    const int b     = slice / NCH;

    const float4* __restrict__ p =
        pred + ((size_t)b * PRED_CH + ch) * HW4 + (size_t)chunk * CHUNK4
             + threadIdx.x;
    const float4* __restrict__ t =
        target + ((size_t)b * TGT_CH + (ch & 1)) * HW4 + (size_t)chunk * CHUNK4
               + threadIdx.x;

    constexpr float NL2E = -1.44269504088896341f;  // -log2(e)
    float acc  = 0.0f;   // sum of max(x,0) - x*t
    float lacc = 0.0f;   // sum of log2( prod4 (1+e) )

    #pragma unroll
    for (int i = 0; i < ITERS; ++i) {
        const float4 x = __ldg(p + i * TPB);
        const float4 y = __ldg(t + i * TPB);

        // e_i = exp(-|x_i|) via EX2 (fabs folds into the FMUL operand)
        const float e0 = exp2f(fabsf(x.x) * NL2E);
        const float e1 = exp2f(fabsf(x.y) * NL2E);
        const float e2 = exp2f(fabsf(x.z) * NL2E);
        const float e3 = exp2f(fabsf(x.w) * NL2E);

        // prod4 (1+e_i): FADD + 3 FFMA (pr = pr*e + pr)
        float pr = 1.0f + e0;
        pr = fmaf(pr, e1, pr);
        pr = fmaf(pr, e2, pr);
        pr = fmaf(pr, e3, pr);
        lacc += __log2f(pr);                 // one LG2 per 4 elements

        acc += fmaxf(x.x, 0.0f); acc = fmaf(-x.x, y.x, acc);
        acc += fmaxf(x.y, 0.0f); acc = fmaf(-x.y, y.y, acc);
        acc += fmaxf(x.z, 0.0f); acc = fmaf(-x.z, y.z, acc);
        acc += fmaxf(x.w, 0.0f); acc = fmaf(-x.w, y.w, acc);
    }

    // fold: total = acc + ln2 * lacc
    const float v = block_reduce(fmaf(0.693147180559945f, lacc, acc));

    // Last-block-done deterministic finalize.
    __shared__ bool s_last;
    if (threadIdx.x == 0) {
        g_partials[bid] = v;
        __threadfence();
        unsigned int n = atomicAdd(&g_count, 1u);
        s_last = (n == (unsigned int)(NBLOCKS - 1));
    }
    __syncthreads();

    if (s_last) {
        __threadfence();
        float a = 0.0f;
        #pragma unroll
        for (int i = threadIdx.x; i < NBLOCKS; i += TPB)
            a += g_partials[i];
        const float total = block_reduce(a);
        if (threadIdx.x == 0) {
            out[0] = total * (1.0f / 9.0f);  // / NUM_OBJ_CLS
            g_count = 0;                     // reset for graph replays
        }
    }
}

extern "C" void kernel_launch(void* const* d_in, const int* in_sizes, int n_in,
                              void* d_out, int out_size) {
    (void)in_sizes; (void)n_in; (void)out_size;
    const float4* pred   = (const float4*)d_in[0];
    const float4* target = (const float4*)d_in[1];
    float* out = (float*)d_out;

    rpn_bce_fused<<<NBLOCKS, TPB>>>(pred, target, out);
}